// round 13
// baseline (speedup 1.0000x reference)
#include <cuda_runtime.h>
#include <cstdint>

#define EMB 256
#define HID 64
#define MAXN 100000
#define MAXQ 8192
#define BCAP 64
#define NB   296            // persistent grid: 2 blocks/SM on 148 SMs, guaranteed resident

// ---------------- scratch (device globals; zero-initialized) ----------------
__device__ int      g_slot[MAXN];          // node -> 0 or slot+1; restored each run
__device__ int      g_qslot[MAXQ];         // query i -> slot (winner index)
__device__ int      g_cnt[MAXQ];           // edges per slot
__device__ int2     g_bin[MAXQ][BCAP];     // (src, w bits) per slot
__device__ uint32_t g_atf[MAXQ][2 * EMB];  // A rows: [tf32 emb | tf32 agg]
__device__ float    g_c[MAXQ];             // per-slot sum_e w_e
__device__ uint32_t g_Wtf[2][HID * EMB];   // tf32-converted Ws, Wn
__device__ unsigned g_launch;              // monotonic launch counter
__device__ unsigned g_bar;                 // monotonic barrier arrivals

__device__ __forceinline__ uint32_t f2tf32(float x) {
    uint32_t r; asm("cvt.rna.tf32.f32 %0, %1;" : "=r"(r) : "f"(x)); return r;
}
__device__ __forceinline__ uint4 tf4(float4 v) {
    return make_uint4(f2tf32(v.x), f2tf32(v.y), f2tf32(v.z), f2tf32(v.w));
}
__device__ __forceinline__ unsigned ldcg_u(const unsigned* p) {
    unsigned v; asm volatile("ld.global.cg.u32 %0, [%1];" : "=r"(v) : "l"(p)); return v;
}
__device__ __forceinline__ int ldcg_i(const int* p) {
    int v; asm volatile("ld.global.cg.s32 %0, [%1];" : "=r"(v) : "l"(p)); return v;
}
__device__ __forceinline__ float ldcg_f(const float* p) {
    float v; asm volatile("ld.global.cg.f32 %0, [%1];" : "=f"(v) : "l"(p)); return v;
}
__device__ __forceinline__ int2 ldcg_i2(const int2* p) {
    int2 v; asm volatile("ld.global.cg.v2.s32 {%0,%1}, [%2];"
                         : "=r"(v.x), "=r"(v.y) : "l"(p)); return v;
}

// ---------------- readout smem layout ----------------
#define QT     32
#define AROW   68
#define ACH    (QT * AROW)
#define BCH    (HID * AROW)
#define CHBUF  (ACH + BCH)              // 6528 u32 per stage buffer
#define AUX_O  (2 * CHBUF)
#define RM_SMEM ((AUX_O + 224) * 4)     // ~53 KB

__global__ void __launch_bounds__(256) k_all(
    const float* __restrict__ emb, const float* __restrict__ ew,
    const float* __restrict__ Ws,  const float* __restrict__ bs,
    const float* __restrict__ Wn,  const float* __restrict__ bn,
    const float* __restrict__ Wr,  const float* __restrict__ br,
    const int* __restrict__ src,   const int* __restrict__ dst,
    const int* __restrict__ query, float* __restrict__ out, int E, int Q)
{
    extern __shared__ float sm[];
    __shared__ unsigned sh_epoch;

    int tid = threadIdx.x;
    int bid = blockIdx.x;

    if (tid == 0) sh_epoch = atomicAdd(&g_launch, 1u) / NB;  // all blocks of this
    __syncthreads();                                          // launch agree on epoch
    unsigned bar_base = sh_epoch * 3u * NB;

#define GBAR(K) { \
    __syncthreads(); \
    if (tid == 0) { \
        __threadfence(); \
        atomicAdd(&g_bar, 1u); \
        unsigned target = bar_base + (unsigned)((K) + 1) * NB; \
        while ((int)(ldcg_u(&g_bar) - target) < 0) __nanosleep(64); \
        __threadfence(); \
    } \
    __syncthreads(); }

    // ======== P0: mark queries, zero counters, convert weights ========
    {
        int i = bid * 256 + tid;                 // 75776 threads >= 32768 items
        if (i < MAXQ) {
            g_cnt[i] = 0;
            if (i < Q) {
                int node = query[i];
                int old = atomicCAS(&g_slot[node], 0, i + 1);
                g_qslot[i] = (old == 0) ? i : (old - 1);
            }
        }
        if (i < HID * EMB) {
            g_Wtf[0][i] = f2tf32(Ws[i]);
            g_Wtf[1][i] = f2tf32(Wn[i]);
        }
    }
    GBAR(0)

    // ======== P1: scan edges, bin hits by dst slot ========
    for (int e = bid * 256 + tid; e < E; e += NB * 256) {
        int m = ldcg_i(&g_slot[dst[e]]);
        if (m > 0) {
            int sl = m - 1;
            int pos = atomicAdd(&g_cnt[sl], 1);
            if (pos < BCAP) g_bin[sl][pos] = make_int2(src[e], __float_as_int(ew[e]));
        }
    }
    GBAR(1)

    // ======== P2: warp per slot -> complete tf32 A row ========
    {
        int lane = tid & 31;
        int gwarp = bid * 8 + (tid >> 5);
        for (int slot = gwarp; slot < Q; slot += NB * 8) {
            int cnt = min(ldcg_i(&g_cnt[slot]), BCAP);
            const int2* bin = g_bin[slot];

            const float4* er = (const float4*)(emb + (size_t)query[slot] * EMB);
            float4 e0 = er[lane], e1 = er[lane + 32];

            float4 a0 = make_float4(0.f, 0.f, 0.f, 0.f);
            float4 a1 = make_float4(0.f, 0.f, 0.f, 0.f);
            float  wsum = 0.f;

            int j = 0;
            for (; j + 4 <= cnt; j += 4) {
                int2 b0 = ldcg_i2(&bin[j]),     b1 = ldcg_i2(&bin[j + 1]);
                int2 b2 = ldcg_i2(&bin[j + 2]), b3 = ldcg_i2(&bin[j + 3]);
                const float4* p0 = (const float4*)(emb + (size_t)b0.x * EMB);
                const float4* p1 = (const float4*)(emb + (size_t)b1.x * EMB);
                const float4* p2 = (const float4*)(emb + (size_t)b2.x * EMB);
                const float4* p3 = (const float4*)(emb + (size_t)b3.x * EMB);
                float4 u00 = p0[lane], u01 = p0[lane + 32];
                float4 u10 = p1[lane], u11 = p1[lane + 32];
                float4 u20 = p2[lane], u21 = p2[lane + 32];
                float4 u30 = p3[lane], u31 = p3[lane + 32];
                float w0 = __int_as_float(b0.y), w1 = __int_as_float(b1.y);
                float w2 = __int_as_float(b2.y), w3 = __int_as_float(b3.y);
                a0.x = fmaf(w0, u00.x, a0.x); a0.y = fmaf(w0, u00.y, a0.y);
                a0.z = fmaf(w0, u00.z, a0.z); a0.w = fmaf(w0, u00.w, a0.w);
                a1.x = fmaf(w0, u01.x, a1.x); a1.y = fmaf(w0, u01.y, a1.y);
                a1.z = fmaf(w0, u01.z, a1.z); a1.w = fmaf(w0, u01.w, a1.w);
                a0.x = fmaf(w1, u10.x, a0.x); a0.y = fmaf(w1, u10.y, a0.y);
                a0.z = fmaf(w1, u10.z, a0.z); a0.w = fmaf(w1, u10.w, a0.w);
                a1.x = fmaf(w1, u11.x, a1.x); a1.y = fmaf(w1, u11.y, a1.y);
                a1.z = fmaf(w1, u11.z, a1.z); a1.w = fmaf(w1, u11.w, a1.w);
                a0.x = fmaf(w2, u20.x, a0.x); a0.y = fmaf(w2, u20.y, a0.y);
                a0.z = fmaf(w2, u20.z, a0.z); a0.w = fmaf(w2, u20.w, a0.w);
                a1.x = fmaf(w2, u21.x, a1.x); a1.y = fmaf(w2, u21.y, a1.y);
                a1.z = fmaf(w2, u21.z, a1.z); a1.w = fmaf(w2, u21.w, a1.w);
                a0.x = fmaf(w3, u30.x, a0.x); a0.y = fmaf(w3, u30.y, a0.y);
                a0.z = fmaf(w3, u30.z, a0.z); a0.w = fmaf(w3, u30.w, a0.w);
                a1.x = fmaf(w3, u31.x, a1.x); a1.y = fmaf(w3, u31.y, a1.y);
                a1.z = fmaf(w3, u31.z, a1.z); a1.w = fmaf(w3, u31.w, a1.w);
                wsum += w0 + w1 + w2 + w3;
            }
            for (; j < cnt; ++j) {
                int2 b0 = ldcg_i2(&bin[j]);
                float w0 = __int_as_float(b0.y);
                const float4* p0 = (const float4*)(emb + (size_t)b0.x * EMB);
                float4 u00 = p0[lane], u01 = p0[lane + 32];
                a0.x = fmaf(w0, u00.x, a0.x); a0.y = fmaf(w0, u00.y, a0.y);
                a0.z = fmaf(w0, u00.z, a0.z); a0.w = fmaf(w0, u00.w, a0.w);
                a1.x = fmaf(w0, u01.x, a1.x); a1.y = fmaf(w0, u01.y, a1.y);
                a1.z = fmaf(w0, u01.z, a1.z); a1.w = fmaf(w0, u01.w, a1.w);
                wsum += w0;
            }

            uint4* arow = (uint4*)g_atf[slot];   // [0,64) emb, [64,128) agg
            arow[lane]           = tf4(e0);
            arow[lane + 32]      = tf4(e1);
            arow[64 + lane]      = tf4(a0);
            arow[64 + 32 + lane] = tf4(a1);
            if (lane == 0) g_c[slot] = wsum;
        }
    }
    GBAR(2)

    // ======== P3: tensor-core readout ========
    {
        uint32_t* SB = (uint32_t*)sm;               // [2][CHBUF]: A then B
        int*   nodes = (int*)(sm + AUX_O);
        int*   slots = nodes + QT;
        float* csm   = (float*)(slots + QT);
        float* rsum  = csm + QT;                    // [4][QT]

        uint32_t smem_u32;
        asm("{ .reg .u64 t; cvta.to.shared.u64 t, %1; cvt.u32.u64 %0, t; }"
            : "=r"(smem_u32) : "l"(sm));

        int ntiles = (Q + QT - 1) / QT;
        for (int tile = bid; tile < ntiles; tile += NB) {
            int qbase = tile * QT;

            if (tid < QT) {
                int q = qbase + tid;
                int sl = (q < Q) ? ldcg_i(&g_qslot[q]) : 0;
                nodes[tid] = (q < Q) ? query[q] : query[0];
                slots[tid] = sl;
                csm[tid]   = ldcg_f(&g_c[sl]);
            }
            __syncthreads();

#define STAGE(C, BUF) { \
    _Pragma("unroll") \
    for (int it = 0; it < 2; ++it) { \
        int idx = tid + it * 256, row = idx >> 4, c4 = idx & 15; \
        const uint32_t* srcp = g_atf[slots[row]] + (C) * 64 + c4 * 4; \
        uint32_t dstp = smem_u32 + (uint32_t)((BUF) * CHBUF + row * AROW + c4 * 4) * 4u; \
        asm volatile("cp.async.cg.shared.global [%0], [%1], 16;" :: "r"(dstp), "l"(srcp)); \
    } \
    const uint32_t* Wp = g_Wtf[(C) < 4 ? 0 : 1]; \
    int kc = ((C) & 3) * 64; \
    _Pragma("unroll") \
    for (int it = 0; it < 4; ++it) { \
        int idx = tid + it * 256, o = idx >> 4, c4 = idx & 15; \
        const uint32_t* srcp = Wp + o * EMB + kc + c4 * 4; \
        uint32_t dstp = smem_u32 + (uint32_t)((BUF) * CHBUF + ACH + o * AROW + c4 * 4) * 4u; \
        asm volatile("cp.async.cg.shared.global [%0], [%1], 16;" :: "r"(dstp), "l"(srcp)); \
    } \
    asm volatile("cp.async.commit_group;"); }

            int lane = tid & 31;
            int wm = (tid >> 5) >> 2;
            int wn = (tid >> 5) & 3;
            int g  = lane >> 2, t = lane & 3;

            float acc[2][4];
#pragma unroll
            for (int a = 0; a < 2; ++a)
#pragma unroll
                for (int b = 0; b < 4; ++b) acc[a][b] = 0.f;

            STAGE(0, 0)

#pragma unroll
            for (int c = 0; c < 8; ++c) {
                if (c < 7) STAGE(c + 1, (c + 1) & 1)
                if (c < 7) { asm volatile("cp.async.wait_group 1;"); }
                else       { asm volatile("cp.async.wait_group 0;"); }
                __syncthreads();

                const uint32_t* ab = SB + (c & 1) * CHBUF + (wm * 16 + g) * AROW + t;
                const uint32_t* bb = SB + (c & 1) * CHBUF + ACH + (wn * 16 + g) * AROW + t;
#pragma unroll
                for (int ks = 0; ks < 8; ++ks) {
                    int k0 = ks * 8;
                    uint32_t a0 = ab[k0];
                    uint32_t a1 = ab[k0 + 8 * AROW];
                    uint32_t a2 = ab[k0 + 4];
                    uint32_t a3 = ab[k0 + 8 * AROW + 4];
#pragma unroll
                    for (int nt = 0; nt < 2; ++nt) {
                        uint32_t b0 = bb[k0 + nt * 8 * AROW];
                        uint32_t b1 = bb[k0 + nt * 8 * AROW + 4];
                        asm("mma.sync.aligned.m16n8k8.row.col.f32.tf32.tf32.f32 "
                            "{%0,%1,%2,%3}, {%4,%5,%6,%7}, {%8,%9}, {%0,%1,%2,%3};"
                            : "+f"(acc[nt][0]), "+f"(acc[nt][1]),
                              "+f"(acc[nt][2]), "+f"(acc[nt][3])
                            : "r"(a0), "r"(a1), "r"(a2), "r"(a3), "r"(b0), "r"(b1));
                    }
                }
                __syncthreads();
            }

            int qr0 = wm * 16 + g, qr1 = qr0 + 8;
            float cc0 = csm[qr0], cc1 = csm[qr1];
            float l0 = 0.f, l1 = 0.f;
#pragma unroll
            for (int nt = 0; nt < 2; ++nt) {
                int o0 = wn * 16 + nt * 8 + 2 * t;
                float b_s0 = bs[o0], b_s1 = bs[o0 + 1];
                float b_n0 = bn[o0], b_n1 = bn[o0 + 1];
                float w_r0 = Wr[o0], w_r1 = Wr[o0 + 1];
                l0 += w_r0 * fmaxf(acc[nt][0] + b_s0 + cc0 * b_n0, 0.f)
                    + w_r1 * fmaxf(acc[nt][1] + b_s1 + cc0 * b_n1, 0.f);
                l1 += w_r0 * fmaxf(acc[nt][2] + b_s0 + cc1 * b_n0, 0.f)
                    + w_r1 * fmaxf(acc[nt][3] + b_s1 + cc1 * b_n1, 0.f);
            }
            l0 += __shfl_xor_sync(0xffffffffu, l0, 1);
            l0 += __shfl_xor_sync(0xffffffffu, l0, 2);
            l1 += __shfl_xor_sync(0xffffffffu, l1, 1);
            l1 += __shfl_xor_sync(0xffffffffu, l1, 2);
            if (t == 0) {
                rsum[wn * QT + qr0] = l0;
                rsum[wn * QT + qr1] = l1;
            }
            __syncthreads();
            if (tid < QT) {
                int q = qbase + tid;
                if (q < Q) {
                    out[q] = rsum[tid] + rsum[QT + tid] + rsum[2 * QT + tid]
                           + rsum[3 * QT + tid] + br[0];
                    g_slot[nodes[tid]] = 0;   // restore for next replay
                }
            }
            __syncthreads();
        }
    }
}

// ---------------- launch ----------------
extern "C" void kernel_launch(void* const* d_in, const int* in_sizes, int n_in,
                              void* d_out, int out_size) {
    const float* emb = (const float*)d_in[0];
    const float* ew  = (const float*)d_in[1];
    const float* Ws  = (const float*)d_in[2];
    const float* bs  = (const float*)d_in[3];
    const float* Wn  = (const float*)d_in[4];
    const float* bn  = (const float*)d_in[5];
    const float* Wr  = (const float*)d_in[6];
    const float* br  = (const float*)d_in[7];
    const int*   src = (const int*)d_in[8];
    const int*   dst = (const int*)d_in[9];
    const int*   qry = (const int*)d_in[10];

    int E = in_sizes[8];
    int Q = in_sizes[10];

    cudaFuncSetAttribute(k_all, cudaFuncAttributeMaxDynamicSharedMemorySize, RM_SMEM);

    k_all<<<NB, 256, RM_SMEM>>>(emb, ew, Ws, bs, Wn, bn, Wr, br, src, dst, qry,
                                (float*)d_out, E, Q);
}

// round 14
// speedup vs baseline: 1.6425x; 1.6425x over previous
#include <cuda_runtime.h>
#include <cstdint>

#define EMB 256
#define HID 64
#define MAXN 100000
#define MAXQ 8192
#define BCAP 64

// ---------------- scratch (device globals; zero-initialized) ----------------
__device__ int      g_slot[MAXN];          // node -> 0 or slot+1; restored each run
__device__ int      g_qslot[MAXQ];         // query i -> slot (winner index)
__device__ int      g_cnt[MAXQ];           // edges per slot
__device__ int2     g_bin[MAXQ][BCAP];     // (src, w bits) per slot
__device__ uint32_t g_stf[MAXQ * EMB];     // per-slot aggregate, tf32 bits
__device__ float    g_c[MAXQ];             // per-slot sum_e w_e
__device__ uint32_t g_Wtf[2][HID * EMB];   // tf32-converted Ws, Wn

__device__ __forceinline__ uint32_t f2tf32(float x) {
    uint32_t r; asm("cvt.rna.tf32.f32 %0, %1;" : "=r"(r) : "f"(x)); return r;
}
__device__ __forceinline__ uint4 tf4(float4 v) {
    return make_uint4(f2tf32(v.x), f2tf32(v.y), f2tf32(v.z), f2tf32(v.w));
}

// ---------------- k1: mark queries, zero counters, convert weights ----------------
__global__ void k_mark(const int* __restrict__ query,
                       const float* __restrict__ Ws,
                       const float* __restrict__ Wn, int Q) {
    int i = blockIdx.x * blockDim.x + threadIdx.x;     // 0..32767
    if (i < MAXQ) {
        g_cnt[i] = 0;
        if (i < Q) {
            int node = query[i];
            int old = atomicCAS(&g_slot[node], 0, i + 1);
            g_qslot[i] = (old == 0) ? i : (old - 1);
        }
    }
    if (i < HID * EMB) {
        g_Wtf[0][i] = f2tf32(Ws[i]);
        g_Wtf[1][i] = f2tf32(Wn[i]);
    }
}

// ---------------- k2: scan edges 4-at-a-time, bin hits by dst slot ----------------
__global__ void __launch_bounds__(256) k_filter(
    const int* __restrict__ src, const int* __restrict__ dst,
    const float* __restrict__ ew, int E)
{
    int i = blockIdx.x * blockDim.x + threadIdx.x;
    int e0 = i * 4;
    if (e0 >= E) return;

#define FHIT(EIDX, DVAL) { \
    int m = g_slot[DVAL]; \
    if (m > 0) { \
        int sl = m - 1; \
        int pos = atomicAdd(&g_cnt[sl], 1); \
        if (pos < BCAP) g_bin[sl][pos] = make_int2(src[EIDX], __float_as_int(ew[EIDX])); \
    } }

    if (e0 + 3 < E) {
        int4 d4 = *(const int4*)(dst + e0);
        FHIT(e0 + 0, d4.x)
        FHIT(e0 + 1, d4.y)
        FHIT(e0 + 2, d4.z)
        FHIT(e0 + 3, d4.w)
    } else {
        for (int e = e0; e < E; ++e) FHIT(e, dst[e])
    }
#undef FHIT
}

// ---------------- k3: warp per slot, 4-edge unroll, store tf32 agg ----------------
__global__ void __launch_bounds__(256) k_accum(const float* __restrict__ emb, int Q) {
    int slot = (blockIdx.x * blockDim.x + threadIdx.x) >> 5;
    int lane = threadIdx.x & 31;
    if (slot >= Q) return;

    int cnt = min(g_cnt[slot], BCAP);
    const int2* bin = g_bin[slot];

    float4 a0 = make_float4(0.f, 0.f, 0.f, 0.f);
    float4 a1 = make_float4(0.f, 0.f, 0.f, 0.f);
    float  wsum = 0.f;

    int j = 0;
    for (; j + 4 <= cnt; j += 4) {
        int2 b0 = bin[j],     b1 = bin[j + 1];
        int2 b2 = bin[j + 2], b3 = bin[j + 3];
        const float4* p0 = (const float4*)(emb + (size_t)b0.x * EMB);
        const float4* p1 = (const float4*)(emb + (size_t)b1.x * EMB);
        const float4* p2 = (const float4*)(emb + (size_t)b2.x * EMB);
        const float4* p3 = (const float4*)(emb + (size_t)b3.x * EMB);
        float4 u00 = p0[lane], u01 = p0[lane + 32];
        float4 u10 = p1[lane], u11 = p1[lane + 32];
        float4 u20 = p2[lane], u21 = p2[lane + 32];
        float4 u30 = p3[lane], u31 = p3[lane + 32];
        float w0 = __int_as_float(b0.y), w1 = __int_as_float(b1.y);
        float w2 = __int_as_float(b2.y), w3 = __int_as_float(b3.y);
        a0.x = fmaf(w0, u00.x, a0.x); a0.y = fmaf(w0, u00.y, a0.y);
        a0.z = fmaf(w0, u00.z, a0.z); a0.w = fmaf(w0, u00.w, a0.w);
        a1.x = fmaf(w0, u01.x, a1.x); a1.y = fmaf(w0, u01.y, a1.y);
        a1.z = fmaf(w0, u01.z, a1.z); a1.w = fmaf(w0, u01.w, a1.w);
        a0.x = fmaf(w1, u10.x, a0.x); a0.y = fmaf(w1, u10.y, a0.y);
        a0.z = fmaf(w1, u10.z, a0.z); a0.w = fmaf(w1, u10.w, a0.w);
        a1.x = fmaf(w1, u11.x, a1.x); a1.y = fmaf(w1, u11.y, a1.y);
        a1.z = fmaf(w1, u11.z, a1.z); a1.w = fmaf(w1, u11.w, a1.w);
        a0.x = fmaf(w2, u20.x, a0.x); a0.y = fmaf(w2, u20.y, a0.y);
        a0.z = fmaf(w2, u20.z, a0.z); a0.w = fmaf(w2, u20.w, a0.w);
        a1.x = fmaf(w2, u21.x, a1.x); a1.y = fmaf(w2, u21.y, a1.y);
        a1.z = fmaf(w2, u21.z, a1.z); a1.w = fmaf(w2, u21.w, a1.w);
        a0.x = fmaf(w3, u30.x, a0.x); a0.y = fmaf(w3, u30.y, a0.y);
        a0.z = fmaf(w3, u30.z, a0.z); a0.w = fmaf(w3, u30.w, a0.w);
        a1.x = fmaf(w3, u31.x, a1.x); a1.y = fmaf(w3, u31.y, a1.y);
        a1.z = fmaf(w3, u31.z, a1.z); a1.w = fmaf(w3, u31.w, a1.w);
        wsum += w0 + w1 + w2 + w3;
    }
    for (; j < cnt; ++j) {
        int2 b0 = bin[j];
        float w0 = __int_as_float(b0.y);
        const float4* p0 = (const float4*)(emb + (size_t)b0.x * EMB);
        float4 u00 = p0[lane], u01 = p0[lane + 32];
        a0.x = fmaf(w0, u00.x, a0.x); a0.y = fmaf(w0, u00.y, a0.y);
        a0.z = fmaf(w0, u00.z, a0.z); a0.w = fmaf(w0, u00.w, a0.w);
        a1.x = fmaf(w0, u01.x, a1.x); a1.y = fmaf(w0, u01.y, a1.y);
        a1.z = fmaf(w0, u01.z, a1.z); a1.w = fmaf(w0, u01.w, a1.w);
        wsum += w0;
    }

    uint4* srow = (uint4*)(g_stf + (size_t)slot * EMB);
    srow[lane]      = tf4(a0);
    srow[lane + 32] = tf4(a1);
    if (lane == 0) g_c[slot] = wsum;
}

// ---------------- k4: tensor-core readout ----------------
// out[q] = Wr . relu(Ws@emb[node_q] + Wn@agg_q + bs + c_q*bn) + br
// A chunks 0-3 from emb (fp32; cvt at fragment load), 4-7 from g_stf (tf32).
// B from g_Wtf (tf32, no cvt). A+B staged per 64-k chunk, double-buffered
// cp.async, 53 KB smem -> 4 blocks/SM. 256 thr, warp tile m16 x n16.
#define QT     32
#define AROW   68
#define ACH    (QT * AROW)
#define BCH    (HID * AROW)
#define CHBUF  (ACH + BCH)              // 6528 u32 per stage buffer
#define AUX_O  (2 * CHBUF)
#define RM_SMEM ((AUX_O + 224) * 4)     // ~53 KB

__global__ void __launch_bounds__(256) k_readout_mma(
    const float* __restrict__ emb, const float* __restrict__ bs,
    const float* __restrict__ bn,  const float* __restrict__ Wr,
    const float* __restrict__ br,  const int* __restrict__ query,
    float* __restrict__ out, int Q)
{
    extern __shared__ float sm[];
    uint32_t* SB = (uint32_t*)sm;               // [2][CHBUF]: A then B
    int*   nodes = (int*)(sm + AUX_O);
    int*   slots = nodes + QT;
    float* csm   = (float*)(slots + QT);
    float* rsum  = csm + QT;                    // [4][QT]

    int tid   = threadIdx.x;
    int qbase = blockIdx.x * QT;

    if (tid < QT) {
        int q = qbase + tid;
        int sl = (q < Q) ? g_qslot[q] : 0;
        nodes[tid] = (q < Q) ? query[q] : query[0];
        slots[tid] = sl;
        csm[tid]   = g_c[sl];
    }
    __syncthreads();

    uint32_t smem_u32;
    asm("{ .reg .u64 t; cvta.to.shared.u64 t, %1; cvt.u32.u64 %0, t; }"
        : "=r"(smem_u32) : "l"(sm));

    // Stage chunk C (64 k-cols of A and B) into buffer BUF.
#define STAGE(C, BUF) { \
    _Pragma("unroll") \
    for (int it = 0; it < 2; ++it) { \
        int idx = tid + it * 256, row = idx >> 4, c4 = idx & 15; \
        const uint32_t* srcp = ((C) < 4) \
            ? (const uint32_t*)(emb + (size_t)nodes[row] * EMB) + (C) * 64 + c4 * 4 \
            : g_stf + (size_t)slots[row] * EMB + ((C) - 4) * 64 + c4 * 4; \
        uint32_t dstp = smem_u32 + (uint32_t)((BUF) * CHBUF + row * AROW + c4 * 4) * 4u; \
        asm volatile("cp.async.cg.shared.global [%0], [%1], 16;" :: "r"(dstp), "l"(srcp)); \
    } \
    const uint32_t* Wp = g_Wtf[(C) < 4 ? 0 : 1]; \
    int kc = ((C) & 3) * 64; \
    _Pragma("unroll") \
    for (int it = 0; it < 4; ++it) { \
        int idx = tid + it * 256, o = idx >> 4, c4 = idx & 15; \
        const uint32_t* srcp = Wp + o * EMB + kc + c4 * 4; \
        uint32_t dstp = smem_u32 + (uint32_t)((BUF) * CHBUF + ACH + o * AROW + c4 * 4) * 4u; \
        asm volatile("cp.async.cg.shared.global [%0], [%1], 16;" :: "r"(dstp), "l"(srcp)); \
    } \
    asm volatile("cp.async.commit_group;"); }

    int lane = tid & 31;
    int wm = (tid >> 5) >> 2;            // 0..1 : q-range wm*16..+15
    int wn = (tid >> 5) & 3;             // 0..3 : o-range wn*16..+15
    int g  = lane >> 2, t = lane & 3;

    float acc[2][4];
#pragma unroll
    for (int a = 0; a < 2; ++a)
#pragma unroll
        for (int b = 0; b < 4; ++b) acc[a][b] = 0.f;

    STAGE(0, 0)

#pragma unroll
    for (int c = 0; c < 8; ++c) {
        if (c < 7) STAGE(c + 1, (c + 1) & 1)
        if (c < 7) { asm volatile("cp.async.wait_group 1;"); }
        else       { asm volatile("cp.async.wait_group 0;"); }
        __syncthreads();

        const uint32_t* ab = SB + (c & 1) * CHBUF + (wm * 16 + g) * AROW + t;
        const uint32_t* bb = SB + (c & 1) * CHBUF + ACH + (wn * 16 + g) * AROW + t;
#pragma unroll
        for (int ks = 0; ks < 8; ++ks) {
            int k0 = ks * 8;
            uint32_t a0 = ab[k0];
            uint32_t a1 = ab[k0 + 8 * AROW];
            uint32_t a2 = ab[k0 + 4];
            uint32_t a3 = ab[k0 + 8 * AROW + 4];
            if (c < 4) {                       // emb half arrives fp32
                a0 = f2tf32(__uint_as_float(a0));
                a1 = f2tf32(__uint_as_float(a1));
                a2 = f2tf32(__uint_as_float(a2));
                a3 = f2tf32(__uint_as_float(a3));
            }
#pragma unroll
            for (int nt = 0; nt < 2; ++nt) {
                uint32_t b0 = bb[k0 + nt * 8 * AROW];
                uint32_t b1 = bb[k0 + nt * 8 * AROW + 4];
                asm("mma.sync.aligned.m16n8k8.row.col.f32.tf32.tf32.f32 "
                    "{%0,%1,%2,%3}, {%4,%5,%6,%7}, {%8,%9}, {%0,%1,%2,%3};"
                    : "+f"(acc[nt][0]), "+f"(acc[nt][1]),
                      "+f"(acc[nt][2]), "+f"(acc[nt][3])
                    : "r"(a0), "r"(a1), "r"(a2), "r"(a3), "r"(b0), "r"(b1));
            }
        }
        __syncthreads();
    }

    // Epilogue: rows q = wm*16+g (+8); cols o = wn*16 + nt*8 + 2t (+1)
    int qr0 = wm * 16 + g, qr1 = qr0 + 8;
    float cc0 = csm[qr0], cc1 = csm[qr1];
    float l0 = 0.f, l1 = 0.f;
#pragma unroll
    for (int nt = 0; nt < 2; ++nt) {
        int o0 = wn * 16 + nt * 8 + 2 * t;
        float b_s0 = bs[o0], b_s1 = bs[o0 + 1];
        float b_n0 = bn[o0], b_n1 = bn[o0 + 1];
        float w_r0 = Wr[o0], w_r1 = Wr[o0 + 1];
        l0 += w_r0 * fmaxf(acc[nt][0] + b_s0 + cc0 * b_n0, 0.f)
            + w_r1 * fmaxf(acc[nt][1] + b_s1 + cc0 * b_n1, 0.f);
        l1 += w_r0 * fmaxf(acc[nt][2] + b_s0 + cc1 * b_n0, 0.f)
            + w_r1 * fmaxf(acc[nt][3] + b_s1 + cc1 * b_n1, 0.f);
    }
    l0 += __shfl_xor_sync(0xffffffffu, l0, 1);
    l0 += __shfl_xor_sync(0xffffffffu, l0, 2);
    l1 += __shfl_xor_sync(0xffffffffu, l1, 1);
    l1 += __shfl_xor_sync(0xffffffffu, l1, 2);
    if (t == 0) {
        rsum[wn * QT + qr0] = l0;
        rsum[wn * QT + qr1] = l1;
    }
    __syncthreads();
    if (tid < QT) {
        int q = qbase + tid;
        if (q < Q) {
            out[q] = rsum[tid] + rsum[QT + tid] + rsum[2 * QT + tid]
                   + rsum[3 * QT + tid] + br[0];
            g_slot[nodes[tid]] = 0;     // restore for next replay (idempotent)
        }
    }
}

// ---------------- launch ----------------
extern "C" void kernel_launch(void* const* d_in, const int* in_sizes, int n_in,
                              void* d_out, int out_size) {
    const float* emb = (const float*)d_in[0];
    const float* ew  = (const float*)d_in[1];
    const float* Ws  = (const float*)d_in[2];
    const float* bs  = (const float*)d_in[3];
    const float* Wn  = (const float*)d_in[4];
    const float* bn  = (const float*)d_in[5];
    const float* Wr  = (const float*)d_in[6];
    const float* br  = (const float*)d_in[7];
    const int*   src = (const int*)d_in[8];
    const int*   dst = (const int*)d_in[9];
    const int*   qry = (const int*)d_in[10];

    int E = in_sizes[8];
    int Q = in_sizes[10];

    cudaFuncSetAttribute(k_readout_mma, cudaFuncAttributeMaxDynamicSharedMemorySize, RM_SMEM);

    int fthreads = (E + 3) / 4;
    k_mark       <<<128, 256>>>(qry, Ws, Wn, Q);
    k_filter     <<<(fthreads + 255) / 256, 256>>>(src, dst, ew, E);
    k_accum      <<<(Q * 32 + 255) / 256, 256>>>(emb, Q);
    k_readout_mma<<<(Q + QT - 1) / QT, 256, RM_SMEM>>>(emb, bs, bn, Wr, br, qry,
                                                       (float*)d_out, Q);
}

// round 15
// speedup vs baseline: 1.6565x; 1.0086x over previous
#include <cuda_runtime.h>
#include <cstdint>

#define EMB 256
#define HID 64
#define MAXN 100000
#define MAXQ 8192
#define BCAP 64

// ---------------- scratch (device globals; zero-initialized) ----------------
__device__ int      g_slot[MAXN];          // node -> 0 or slot+1; restored each run
__device__ int      g_qslot[MAXQ];         // query i -> slot (winner index)
__device__ int      g_cnt[MAXQ];           // edges per slot
__device__ int2     g_bin[MAXQ][BCAP];     // (src, w bits) per slot
__device__ uint32_t g_Wtf[2][HID * EMB];   // tf32-converted Ws, Wn

__device__ __forceinline__ uint32_t f2tf32(float x) {
    uint32_t r; asm("cvt.rna.tf32.f32 %0, %1;" : "=r"(r) : "f"(x)); return r;
}
__device__ __forceinline__ uint4 tf4(float4 v) {
    return make_uint4(f2tf32(v.x), f2tf32(v.y), f2tf32(v.z), f2tf32(v.w));
}

// ---------------- k1: mark queries, zero counters, convert weights ----------------
__global__ void k_mark(const int* __restrict__ query,
                       const float* __restrict__ Ws,
                       const float* __restrict__ Wn, int Q) {
    int i = blockIdx.x * blockDim.x + threadIdx.x;     // 0..32767
    if (i < MAXQ) {
        g_cnt[i] = 0;
        if (i < Q) {
            int node = query[i];
            int old = atomicCAS(&g_slot[node], 0, i + 1);
            g_qslot[i] = (old == 0) ? i : (old - 1);
        }
    }
    if (i < HID * EMB) {
        g_Wtf[0][i] = f2tf32(Ws[i]);
        g_Wtf[1][i] = f2tf32(Wn[i]);
    }
}

// ---------------- k2: scan edges 4-at-a-time, bin hits by dst slot ----------------
__global__ void __launch_bounds__(256) k_filter(
    const int* __restrict__ src, const int* __restrict__ dst,
    const float* __restrict__ ew, int E)
{
    int i = blockIdx.x * blockDim.x + threadIdx.x;
    int e0 = i * 4;
    if (e0 >= E) return;

#define FHIT(EIDX, DVAL) { \
    int m = g_slot[DVAL]; \
    if (m > 0) { \
        int sl = m - 1; \
        int pos = atomicAdd(&g_cnt[sl], 1); \
        if (pos < BCAP) g_bin[sl][pos] = make_int2(src[EIDX], __float_as_int(ew[EIDX])); \
    } }

    if (e0 + 3 < E) {
        int4 d4 = *(const int4*)(dst + e0);
        FHIT(e0 + 0, d4.x)
        FHIT(e0 + 1, d4.y)
        FHIT(e0 + 2, d4.z)
        FHIT(e0 + 3, d4.w)
    } else {
        for (int e = e0; e < E; ++e) FHIT(e, dst[e])
    }
#undef FHIT
}

// ---------------- k3: fused gather + tensor-core readout ----------------
// out[q] = Wr . relu(Ws@emb[node_q] + Wn@agg_q + bs + c_q*bn) + br
// Per block of 32 queries:
//   gather: 8 warps x 4 slots each aggregate g_bin edges into the persistent
//           smem AGG region (A k-chunks 4..7, tf32), overlapping the chunk-0
//           weight/emb cp.async stage.
//   mma:    8 chunks of 64 k. Chunks 0-3: A = emb (fp32 staged, cvt at frag
//           load); chunks 4-7: A = AGG (tf32, no staging). B = g_Wtf, double
//           buffered cp.async. Warp tile m16 x n16.
#define QT     32
#define AROW   68
#define ACH    (QT * AROW)              // 2176 u32
#define BCH    (HID * AROW)             // 4352 u32
#define CHBUF  (ACH + BCH)              // 6528 u32 per stage buffer
#define AGG_O  0                        // [4][QT][AROW]
#define SB_O   (4 * ACH)                // double buffer base (8704)
#define AUX_O  (SB_O + 2 * CHBUF)       // + nodes[32] slots[32] csm[32] rsum[128]
#define RM_SMEM ((AUX_O + 224) * 4)     // ~88 KB -> 2 blocks/SM

__global__ void __launch_bounds__(256) k_fused(
    const float* __restrict__ emb, const float* __restrict__ bs,
    const float* __restrict__ bn,  const float* __restrict__ Wr,
    const float* __restrict__ br,  const int* __restrict__ query,
    float* __restrict__ out, int Q)
{
    extern __shared__ float sm[];
    uint32_t* AGG = (uint32_t*)sm;              // agg A chunks (k 256..511)
    uint32_t* SB  = (uint32_t*)sm + SB_O;       // [2][CHBUF]: A-emb then B
    int*   nodes = (int*)(sm + AUX_O);
    int*   slots = nodes + QT;
    float* csm   = (float*)(slots + QT);
    float* rsum  = csm + QT;                    // [4][QT]

    int tid   = threadIdx.x;
    int qbase = blockIdx.x * QT;

    if (tid < QT) {
        int q = qbase + tid;
        int sl = (q < Q) ? g_qslot[q] : 0;
        nodes[tid] = (q < Q) ? query[q] : query[0];
        slots[tid] = sl;
    }
    __syncthreads();

    uint32_t smem_u32;
    asm("{ .reg .u64 t; cvta.to.shared.u64 t, %1; cvt.u32.u64 %0, t; }"
        : "=r"(smem_u32) : "l"(sm));

    // Stage chunk C: A-emb part only for C<4; B part always.
#define STAGE(C, BUF) { \
    if ((C) < 4) { \
        _Pragma("unroll") \
        for (int it = 0; it < 2; ++it) { \
            int idx = tid + it * 256, row = idx >> 4, c4 = idx & 15; \
            const uint32_t* srcp = \
                (const uint32_t*)(emb + (size_t)nodes[row] * EMB) + (C) * 64 + c4 * 4; \
            uint32_t dstp = smem_u32 + (uint32_t)(SB_O + (BUF) * CHBUF + row * AROW + c4 * 4) * 4u; \
            asm volatile("cp.async.cg.shared.global [%0], [%1], 16;" :: "r"(dstp), "l"(srcp)); \
        } \
    } \
    const uint32_t* Wp = g_Wtf[(C) < 4 ? 0 : 1]; \
    int kc = ((C) & 3) * 64; \
    _Pragma("unroll") \
    for (int it = 0; it < 4; ++it) { \
        int idx = tid + it * 256, o = idx >> 4, c4 = idx & 15; \
        const uint32_t* srcp = Wp + o * EMB + kc + c4 * 4; \
        uint32_t dstp = smem_u32 + (uint32_t)(SB_O + (BUF) * CHBUF + ACH + o * AROW + c4 * 4) * 4u; \
        asm volatile("cp.async.cg.shared.global [%0], [%1], 16;" :: "r"(dstp), "l"(srcp)); \
    } \
    asm volatile("cp.async.commit_group;"); }

    STAGE(0, 0)     // overlaps the gather below

    // ---- gather phase: warp w aggregates slots (local rows) 4w..4w+3 ----
    {
        int lane = tid & 31;
        int w    = tid >> 5;
        for (int rr = 0; rr < 4; ++rr) {
            int r = w * 4 + rr;
            int slot = slots[r];
            int cnt = min(g_cnt[slot], BCAP);
            const int2* bin = g_bin[slot];

            float4 a0 = make_float4(0.f, 0.f, 0.f, 0.f);
            float4 a1 = make_float4(0.f, 0.f, 0.f, 0.f);
            float  wsum = 0.f;

            int j = 0;
            for (; j + 4 <= cnt; j += 4) {
                int2 b0 = bin[j],     b1 = bin[j + 1];
                int2 b2 = bin[j + 2], b3 = bin[j + 3];
                const float4* p0 = (const float4*)(emb + (size_t)b0.x * EMB);
                const float4* p1 = (const float4*)(emb + (size_t)b1.x * EMB);
                const float4* p2 = (const float4*)(emb + (size_t)b2.x * EMB);
                const float4* p3 = (const float4*)(emb + (size_t)b3.x * EMB);
                float4 u00 = p0[lane], u01 = p0[lane + 32];
                float4 u10 = p1[lane], u11 = p1[lane + 32];
                float4 u20 = p2[lane], u21 = p2[lane + 32];
                float4 u30 = p3[lane], u31 = p3[lane + 32];
                float w0 = __int_as_float(b0.y), w1 = __int_as_float(b1.y);
                float w2 = __int_as_float(b2.y), w3 = __int_as_float(b3.y);
                a0.x = fmaf(w0, u00.x, a0.x); a0.y = fmaf(w0, u00.y, a0.y);
                a0.z = fmaf(w0, u00.z, a0.z); a0.w = fmaf(w0, u00.w, a0.w);
                a1.x = fmaf(w0, u01.x, a1.x); a1.y = fmaf(w0, u01.y, a1.y);
                a1.z = fmaf(w0, u01.z, a1.z); a1.w = fmaf(w0, u01.w, a1.w);
                a0.x = fmaf(w1, u10.x, a0.x); a0.y = fmaf(w1, u10.y, a0.y);
                a0.z = fmaf(w1, u10.z, a0.z); a0.w = fmaf(w1, u10.w, a0.w);
                a1.x = fmaf(w1, u11.x, a1.x); a1.y = fmaf(w1, u11.y, a1.y);
                a1.z = fmaf(w1, u11.z, a1.z); a1.w = fmaf(w1, u11.w, a1.w);
                a0.x = fmaf(w2, u20.x, a0.x); a0.y = fmaf(w2, u20.y, a0.y);
                a0.z = fmaf(w2, u20.z, a0.z); a0.w = fmaf(w2, u20.w, a0.w);
                a1.x = fmaf(w2, u21.x, a1.x); a1.y = fmaf(w2, u21.y, a1.y);
                a1.z = fmaf(w2, u21.z, a1.z); a1.w = fmaf(w2, u21.w, a1.w);
                a0.x = fmaf(w3, u30.x, a0.x); a0.y = fmaf(w3, u30.y, a0.y);
                a0.z = fmaf(w3, u30.z, a0.z); a0.w = fmaf(w3, u30.w, a0.w);
                a1.x = fmaf(w3, u31.x, a1.x); a1.y = fmaf(w3, u31.y, a1.y);
                a1.z = fmaf(w3, u31.z, a1.z); a1.w = fmaf(w3, u31.w, a1.w);
                wsum += w0 + w1 + w2 + w3;
            }
            for (; j < cnt; ++j) {
                int2 b0 = bin[j];
                float w0 = __int_as_float(b0.y);
                const float4* p0 = (const float4*)(emb + (size_t)b0.x * EMB);
                float4 u00 = p0[lane], u01 = p0[lane + 32];
                a0.x = fmaf(w0, u00.x, a0.x); a0.y = fmaf(w0, u00.y, a0.y);
                a0.z = fmaf(w0, u00.z, a0.z); a0.w = fmaf(w0, u00.w, a0.w);
                a1.x = fmaf(w0, u01.x, a1.x); a1.y = fmaf(w0, u01.y, a1.y);
                a1.z = fmaf(w0, u01.z, a1.z); a1.w = fmaf(w0, u01.w, a1.w);
                wsum += w0;
            }

            // a0 -> agg cols 4*lane (chunks 0-1 of AGG), a1 -> cols 128+4*lane
            int ch0 = lane >> 4, off = (4 * lane) & 63;
            *(uint4*)&AGG[(ch0)     * ACH + r * AROW + off] = tf4(a0);
            *(uint4*)&AGG[(2 + ch0) * ACH + r * AROW + off] = tf4(a1);
            if (lane == 0) csm[r] = wsum;
        }
    }
    __syncthreads();    // AGG + csm visible

    // ---- MMA phase ----
    int lane = tid & 31;
    int wm = (tid >> 5) >> 2;            // 0..1 : q-range wm*16..+15
    int wn = (tid >> 5) & 3;             // 0..3 : o-range wn*16..+15
    int g  = lane >> 2, t = lane & 3;

    float acc[2][4];
#pragma unroll
    for (int a = 0; a < 2; ++a)
#pragma unroll
        for (int b = 0; b < 4; ++b) acc[a][b] = 0.f;

#pragma unroll
    for (int c = 0; c < 8; ++c) {
        if (c < 7) STAGE(c + 1, (c + 1) & 1)
        if (c < 7) { asm volatile("cp.async.wait_group 1;"); }
        else       { asm volatile("cp.async.wait_group 0;"); }
        __syncthreads();

        const uint32_t* ab = (c < 4)
            ? SB + (c & 1) * CHBUF + (wm * 16 + g) * AROW + t
            : AGG + (c - 4) * ACH + (wm * 16 + g) * AROW + t;
        const uint32_t* bb = SB + (c & 1) * CHBUF + ACH + (wn * 16 + g) * AROW + t;
#pragma unroll
        for (int ks = 0; ks < 8; ++ks) {
            int k0 = ks * 8;
            uint32_t a0 = ab[k0];
            uint32_t a1 = ab[k0 + 8 * AROW];
            uint32_t a2 = ab[k0 + 4];
            uint32_t a3 = ab[k0 + 8 * AROW + 4];
            if (c < 4) {                       // emb half arrives fp32
                a0 = f2tf32(__uint_as_float(a0));
                a1 = f2tf32(__uint_as_float(a1));
                a2 = f2tf32(__uint_as_float(a2));
                a3 = f2tf32(__uint_as_float(a3));
            }
#pragma unroll
            for (int nt = 0; nt < 2; ++nt) {
                uint32_t b0 = bb[k0 + nt * 8 * AROW];
                uint32_t b1 = bb[k0 + nt * 8 * AROW + 4];
                asm("mma.sync.aligned.m16n8k8.row.col.f32.tf32.tf32.f32 "
                    "{%0,%1,%2,%3}, {%4,%5,%6,%7}, {%8,%9}, {%0,%1,%2,%3};"
                    : "+f"(acc[nt][0]), "+f"(acc[nt][1]),
                      "+f"(acc[nt][2]), "+f"(acc[nt][3])
                    : "r"(a0), "r"(a1), "r"(a2), "r"(a3), "r"(b0), "r"(b1));
            }
        }
        __syncthreads();
    }

    // ---- epilogue ----
    int qr0 = wm * 16 + g, qr1 = qr0 + 8;
    float cc0 = csm[qr0], cc1 = csm[qr1];
    float l0 = 0.f, l1 = 0.f;
#pragma unroll
    for (int nt = 0; nt < 2; ++nt) {
        int o0 = wn * 16 + nt * 8 + 2 * t;
        float b_s0 = bs[o0], b_s1 = bs[o0 + 1];
        float b_n0 = bn[o0], b_n1 = bn[o0 + 1];
        float w_r0 = Wr[o0], w_r1 = Wr[o0 + 1];
        l0 += w_r0 * fmaxf(acc[nt][0] + b_s0 + cc0 * b_n0, 0.f)
            + w_r1 * fmaxf(acc[nt][1] + b_s1 + cc0 * b_n1, 0.f);
        l1 += w_r0 * fmaxf(acc[nt][2] + b_s0 + cc1 * b_n0, 0.f)
            + w_r1 * fmaxf(acc[nt][3] + b_s1 + cc1 * b_n1, 0.f);
    }
    l0 += __shfl_xor_sync(0xffffffffu, l0, 1);
    l0 += __shfl_xor_sync(0xffffffffu, l0, 2);
    l1 += __shfl_xor_sync(0xffffffffu, l1, 1);
    l1 += __shfl_xor_sync(0xffffffffu, l1, 2);
    if (t == 0) {
        rsum[wn * QT + qr0] = l0;
        rsum[wn * QT + qr1] = l1;
    }
    __syncthreads();
    if (tid < QT) {
        int q = qbase + tid;
        if (q < Q) {
            out[q] = rsum[tid] + rsum[QT + tid] + rsum[2 * QT + tid]
                   + rsum[3 * QT + tid] + br[0];
            g_slot[nodes[tid]] = 0;     // restore for next replay (idempotent)
        }
    }
}

// ---------------- launch ----------------
extern "C" void kernel_launch(void* const* d_in, const int* in_sizes, int n_in,
                              void* d_out, int out_size) {
    const float* emb = (const float*)d_in[0];
    const float* ew  = (const float*)d_in[1];
    const float* Ws  = (const float*)d_in[2];
    const float* bs  = (const float*)d_in[3];
    const float* Wn  = (const float*)d_in[4];
    const float* bn  = (const float*)d_in[5];
    const float* Wr  = (const float*)d_in[6];
    const float* br  = (const float*)d_in[7];
    const int*   src = (const int*)d_in[8];
    const int*   dst = (const int*)d_in[9];
    const int*   qry = (const int*)d_in[10];

    int E = in_sizes[8];
    int Q = in_sizes[10];

    cudaFuncSetAttribute(k_fused, cudaFuncAttributeMaxDynamicSharedMemorySize, RM_SMEM);

    int fthreads = (E + 3) / 4;
    k_mark  <<<128, 256>>>(qry, Ws, Wn, Q);
    k_filter<<<(fthreads + 255) / 256, 256>>>(src, dst, ew, E);
    k_fused <<<(Q + QT - 1) / QT, 256, RM_SMEM>>>(emb, bs, bn, Wr, br, qry,
                                                  (float*)d_out, Q);
}

// round 16
// speedup vs baseline: 1.6814x; 1.0150x over previous
#include <cuda_runtime.h>
#include <cstdint>

#define EMB 256
#define HID 64
#define MAXN 100000
#define MAXQ 8192
#define BCAP 64

// ---------------- scratch (device globals; zero-initialized) ----------------
__device__ int      g_slot[MAXN];          // node -> 0 or slot+1; restored each run
__device__ int      g_qslot[MAXQ];         // query i -> slot (winner index)
__device__ int      g_cnt[MAXQ];           // edges per slot
__device__ int2     g_bin[MAXQ][BCAP];     // (src, w bits) per slot
__device__ uint32_t g_Wtf[2][HID * EMB];   // tf32-converted Ws, Wn

__device__ __forceinline__ uint32_t f2tf32(float x) {
    uint32_t r; asm("cvt.rna.tf32.f32 %0, %1;" : "=r"(r) : "f"(x)); return r;
}
__device__ __forceinline__ uint4 tf4(float4 v) {
    return make_uint4(f2tf32(v.x), f2tf32(v.y), f2tf32(v.z), f2tf32(v.w));
}

// ---------------- k1: minimal ordering prefix: mark queries + zero counters ----------------
__global__ void k_mark(const int* __restrict__ query, int Q) {
    int i = blockIdx.x * blockDim.x + threadIdx.x;     // 0..MAXQ-1
    if (i < MAXQ) g_cnt[i] = 0;
    if (i < Q) {
        int node = query[i];
        int old = atomicCAS(&g_slot[node], 0, i + 1);
        g_qslot[i] = (old == 0) ? i : (old - 1);
    }
}

// ---------------- k2: edge scan + (extra blocks) weight conversion ----------------
__global__ void __launch_bounds__(256) k_filter(
    const int* __restrict__ src, const int* __restrict__ dst,
    const float* __restrict__ ew, const float* __restrict__ Ws,
    const float* __restrict__ Wn, int E, int fblocks)
{
    int bid = blockIdx.x;
    if (bid >= fblocks) {
        // weight-conversion blocks: 64 blocks x 256 thr = 16384 items
        int i = (bid - fblocks) * 256 + threadIdx.x;
        if (i < HID * EMB) {
            g_Wtf[0][i] = f2tf32(Ws[i]);
            g_Wtf[1][i] = f2tf32(Wn[i]);
        }
        return;
    }

    int i = bid * blockDim.x + threadIdx.x;
    int e0 = i * 4;
    if (e0 >= E) return;

#define FHIT(EIDX, DVAL) { \
    int m = g_slot[DVAL]; \
    if (m > 0) { \
        int sl = m - 1; \
        int pos = atomicAdd(&g_cnt[sl], 1); \
        if (pos < BCAP) g_bin[sl][pos] = make_int2(src[EIDX], __float_as_int(ew[EIDX])); \
    } }

    if (e0 + 3 < E) {
        int4 d4 = *(const int4*)(dst + e0);
        FHIT(e0 + 0, d4.x)
        FHIT(e0 + 1, d4.y)
        FHIT(e0 + 2, d4.z)
        FHIT(e0 + 3, d4.w)
    } else {
        for (int e = e0; e < E; ++e) FHIT(e, dst[e])
    }
#undef FHIT
}

// ---------------- k3: fused gather + tensor-core readout ----------------
// out[q] = Wr . relu(Ws@emb[node_q] + Wn@agg_q + bs + c_q*bn) + br
#define QT     32
#define AROW   68
#define ACH    (QT * AROW)              // 2176 u32
#define BCH    (HID * AROW)             // 4352 u32
#define CHBUF  (ACH + BCH)              // 6528 u32 per stage buffer
#define SB_O   (4 * ACH)                // double buffer base (8704)
#define AUX_O  (SB_O + 2 * CHBUF)       // + nodes[32] slots[32] csm[32] rsum[128]
#define RM_SMEM ((AUX_O + 224) * 4)     // ~88 KB -> 2 blocks/SM

__global__ void __launch_bounds__(256) k_fused(
    const float* __restrict__ emb, const float* __restrict__ bs,
    const float* __restrict__ bn,  const float* __restrict__ Wr,
    const float* __restrict__ br,  const int* __restrict__ query,
    float* __restrict__ out, int Q)
{
    extern __shared__ float sm[];
    uint32_t* AGG = (uint32_t*)sm;              // agg A chunks (k 256..511)
    uint32_t* SB  = (uint32_t*)sm + SB_O;       // [2][CHBUF]: A-emb then B
    int*   nodes = (int*)(sm + AUX_O);
    int*   slots = nodes + QT;
    float* csm   = (float*)(slots + QT);
    float* rsum  = csm + QT;                    // [4][QT]

    int tid   = threadIdx.x;
    int qbase = blockIdx.x * QT;

    if (tid < QT) {
        int q = qbase + tid;
        int sl = (q < Q) ? g_qslot[q] : 0;
        nodes[tid] = (q < Q) ? query[q] : query[0];
        slots[tid] = sl;
    }
    __syncthreads();

    uint32_t smem_u32;
    asm("{ .reg .u64 t; cvta.to.shared.u64 t, %1; cvt.u32.u64 %0, t; }"
        : "=r"(smem_u32) : "l"(sm));

    // Stage chunk C: A-emb part only for C<4; B part always.
#define STAGE(C, BUF) { \
    if ((C) < 4) { \
        _Pragma("unroll") \
        for (int it = 0; it < 2; ++it) { \
            int idx = tid + it * 256, row = idx >> 4, c4 = idx & 15; \
            const uint32_t* srcp = \
                (const uint32_t*)(emb + (size_t)nodes[row] * EMB) + (C) * 64 + c4 * 4; \
            uint32_t dstp = smem_u32 + (uint32_t)(SB_O + (BUF) * CHBUF + row * AROW + c4 * 4) * 4u; \
            asm volatile("cp.async.cg.shared.global [%0], [%1], 16;" :: "r"(dstp), "l"(srcp)); \
        } \
    } \
    const uint32_t* Wp = g_Wtf[(C) < 4 ? 0 : 1]; \
    int kc = ((C) & 3) * 64; \
    _Pragma("unroll") \
    for (int it = 0; it < 4; ++it) { \
        int idx = tid + it * 256, o = idx >> 4, c4 = idx & 15; \
        const uint32_t* srcp = Wp + o * EMB + kc + c4 * 4; \
        uint32_t dstp = smem_u32 + (uint32_t)(SB_O + (BUF) * CHBUF + ACH + o * AROW + c4 * 4) * 4u; \
        asm volatile("cp.async.cg.shared.global [%0], [%1], 16;" :: "r"(dstp), "l"(srcp)); \
    } \
    asm volatile("cp.async.commit_group;"); }

    STAGE(0, 0)     // overlaps the gather below

    // ---- gather phase: warp w aggregates slots (local rows) 4w..4w+3 ----
    {
        int lane = tid & 31;
        int w    = tid >> 5;
        for (int rr = 0; rr < 4; ++rr) {
            int r = w * 4 + rr;
            int slot = slots[r];
            int cnt = min(g_cnt[slot], BCAP);
            const int2* bin = g_bin[slot];

            float4 a0 = make_float4(0.f, 0.f, 0.f, 0.f);
            float4 a1 = make_float4(0.f, 0.f, 0.f, 0.f);
            float  wsum = 0.f;

            int j = 0;
            for (; j + 4 <= cnt; j += 4) {
                int2 b0 = bin[j],     b1 = bin[j + 1];
                int2 b2 = bin[j + 2], b3 = bin[j + 3];
                const float4* p0 = (const float4*)(emb + (size_t)b0.x * EMB);
                const float4* p1 = (const float4*)(emb + (size_t)b1.x * EMB);
                const float4* p2 = (const float4*)(emb + (size_t)b2.x * EMB);
                const float4* p3 = (const float4*)(emb + (size_t)b3.x * EMB);
                float4 u00 = p0[lane], u01 = p0[lane + 32];
                float4 u10 = p1[lane], u11 = p1[lane + 32];
                float4 u20 = p2[lane], u21 = p2[lane + 32];
                float4 u30 = p3[lane], u31 = p3[lane + 32];
                float w0 = __int_as_float(b0.y), w1 = __int_as_float(b1.y);
                float w2 = __int_as_float(b2.y), w3 = __int_as_float(b3.y);
                a0.x = fmaf(w0, u00.x, a0.x); a0.y = fmaf(w0, u00.y, a0.y);
                a0.z = fmaf(w0, u00.z, a0.z); a0.w = fmaf(w0, u00.w, a0.w);
                a1.x = fmaf(w0, u01.x, a1.x); a1.y = fmaf(w0, u01.y, a1.y);
                a1.z = fmaf(w0, u01.z, a1.z); a1.w = fmaf(w0, u01.w, a1.w);
                a0.x = fmaf(w1, u10.x, a0.x); a0.y = fmaf(w1, u10.y, a0.y);
                a0.z = fmaf(w1, u10.z, a0.z); a0.w = fmaf(w1, u10.w, a0.w);
                a1.x = fmaf(w1, u11.x, a1.x); a1.y = fmaf(w1, u11.y, a1.y);
                a1.z = fmaf(w1, u11.z, a1.z); a1.w = fmaf(w1, u11.w, a1.w);
                a0.x = fmaf(w2, u20.x, a0.x); a0.y = fmaf(w2, u20.y, a0.y);
                a0.z = fmaf(w2, u20.z, a0.z); a0.w = fmaf(w2, u20.w, a0.w);
                a1.x = fmaf(w2, u21.x, a1.x); a1.y = fmaf(w2, u21.y, a1.y);
                a1.z = fmaf(w2, u21.z, a1.z); a1.w = fmaf(w2, u21.w, a1.w);
                a0.x = fmaf(w3, u30.x, a0.x); a0.y = fmaf(w3, u30.y, a0.y);
                a0.z = fmaf(w3, u30.z, a0.z); a0.w = fmaf(w3, u30.w, a0.w);
                a1.x = fmaf(w3, u31.x, a1.x); a1.y = fmaf(w3, u31.y, a1.y);
                a1.z = fmaf(w3, u31.z, a1.z); a1.w = fmaf(w3, u31.w, a1.w);
                wsum += w0 + w1 + w2 + w3;
            }
            for (; j < cnt; ++j) {
                int2 b0 = bin[j];
                float w0 = __int_as_float(b0.y);
                const float4* p0 = (const float4*)(emb + (size_t)b0.x * EMB);
                float4 u00 = p0[lane], u01 = p0[lane + 32];
                a0.x = fmaf(w0, u00.x, a0.x); a0.y = fmaf(w0, u00.y, a0.y);
                a0.z = fmaf(w0, u00.z, a0.z); a0.w = fmaf(w0, u00.w, a0.w);
                a1.x = fmaf(w0, u01.x, a1.x); a1.y = fmaf(w0, u01.y, a1.y);
                a1.z = fmaf(w0, u01.z, a1.z); a1.w = fmaf(w0, u01.w, a1.w);
                wsum += w0;
            }

            int ch0 = lane >> 4, off = (4 * lane) & 63;
            *(uint4*)&AGG[(ch0)     * ACH + r * AROW + off] = tf4(a0);
            *(uint4*)&AGG[(2 + ch0) * ACH + r * AROW + off] = tf4(a1);
            if (lane == 0) csm[r] = wsum;
        }
    }
    __syncthreads();    // AGG + csm visible

    // ---- MMA phase ----
    int lane = tid & 31;
    int wm = (tid >> 5) >> 2;            // 0..1 : q-range wm*16..+15
    int wn = (tid >> 5) & 3;             // 0..3 : o-range wn*16..+15
    int g  = lane >> 2, t = lane & 3;

    float acc[2][4];
#pragma unroll
    for (int a = 0; a < 2; ++a)
#pragma unroll
        for (int b = 0; b < 4; ++b) acc[a][b] = 0.f;

#pragma unroll
    for (int c = 0; c < 8; ++c) {
        if (c < 7) STAGE(c + 1, (c + 1) & 1)
        if (c < 7) { asm volatile("cp.async.wait_group 1;"); }
        else       { asm volatile("cp.async.wait_group 0;"); }
        __syncthreads();

        const uint32_t* ab = (c < 4)
            ? SB + (c & 1) * CHBUF + (wm * 16 + g) * AROW + t
            : AGG + (c - 4) * ACH + (wm * 16 + g) * AROW + t;
        const uint32_t* bb = SB + (c & 1) * CHBUF + ACH + (wn * 16 + g) * AROW + t;
#pragma unroll
        for (int ks = 0; ks < 8; ++ks) {
            int k0 = ks * 8;
            uint32_t a0 = ab[k0];
            uint32_t a1 = ab[k0 + 8 * AROW];
            uint32_t a2 = ab[k0 + 4];
            uint32_t a3 = ab[k0 + 8 * AROW + 4];
            if (c < 4) {                       // emb half arrives fp32
                a0 = f2tf32(__uint_as_float(a0));
                a1 = f2tf32(__uint_as_float(a1));
                a2 = f2tf32(__uint_as_float(a2));
                a3 = f2tf32(__uint_as_float(a3));
            }
#pragma unroll
            for (int nt = 0; nt < 2; ++nt) {
                uint32_t b0 = bb[k0 + nt * 8 * AROW];
                uint32_t b1 = bb[k0 + nt * 8 * AROW + 4];
                asm("mma.sync.aligned.m16n8k8.row.col.f32.tf32.tf32.f32 "
                    "{%0,%1,%2,%3}, {%4,%5,%6,%7}, {%8,%9}, {%0,%1,%2,%3};"
                    : "+f"(acc[nt][0]), "+f"(acc[nt][1]),
                      "+f"(acc[nt][2]), "+f"(acc[nt][3])
                    : "r"(a0), "r"(a1), "r"(a2), "r"(a3), "r"(b0), "r"(b1));
            }
        }
        __syncthreads();
    }

    // ---- epilogue ----
    int qr0 = wm * 16 + g, qr1 = qr0 + 8;
    float cc0 = csm[qr0], cc1 = csm[qr1];
    float l0 = 0.f, l1 = 0.f;
#pragma unroll
    for (int nt = 0; nt < 2; ++nt) {
        int o0 = wn * 16 + nt * 8 + 2 * t;
        float b_s0 = bs[o0], b_s1 = bs[o0 + 1];
        float b_n0 = bn[o0], b_n1 = bn[o0 + 1];
        float w_r0 = Wr[o0], w_r1 = Wr[o0 + 1];
        l0 += w_r0 * fmaxf(acc[nt][0] + b_s0 + cc0 * b_n0, 0.f)
            + w_r1 * fmaxf(acc[nt][1] + b_s1 + cc0 * b_n1, 0.f);
        l1 += w_r0 * fmaxf(acc[nt][2] + b_s0 + cc1 * b_n0, 0.f)
            + w_r1 * fmaxf(acc[nt][3] + b_s1 + cc1 * b_n1, 0.f);
    }
    l0 += __shfl_xor_sync(0xffffffffu, l0, 1);
    l0 += __shfl_xor_sync(0xffffffffu, l0, 2);
    l1 += __shfl_xor_sync(0xffffffffu, l1, 1);
    l1 += __shfl_xor_sync(0xffffffffu, l1, 2);
    if (t == 0) {
        rsum[wn * QT + qr0] = l0;
        rsum[wn * QT + qr1] = l1;
    }
    __syncthreads();
    if (tid < QT) {
        int q = qbase + tid;
        if (q < Q) {
            out[q] = rsum[tid] + rsum[QT + tid] + rsum[2 * QT + tid]
                   + rsum[3 * QT + tid] + br[0];
            g_slot[nodes[tid]] = 0;     // restore for next replay (idempotent)
        }
    }
}

// ---------------- launch ----------------
extern "C" void kernel_launch(void* const* d_in, const int* in_sizes, int n_in,
                              void* d_out, int out_size) {
    const float* emb = (const float*)d_in[0];
    const float* ew  = (const float*)d_in[1];
    const float* Ws  = (const float*)d_in[2];
    const float* bs  = (const float*)d_in[3];
    const float* Wn  = (const float*)d_in[4];
    const float* bn  = (const float*)d_in[5];
    const float* Wr  = (const float*)d_in[6];
    const float* br  = (const float*)d_in[7];
    const int*   src = (const int*)d_in[8];
    const int*   dst = (const int*)d_in[9];
    const int*   qry = (const int*)d_in[10];

    int E = in_sizes[8];
    int Q = in_sizes[10];

    cudaFuncSetAttribute(k_fused, cudaFuncAttributeMaxDynamicSharedMemorySize, RM_SMEM);

    int fthreads = (E + 3) / 4;
    int fblocks  = (fthreads + 255) / 256;
    k_mark  <<<(MAXQ + 255) / 256, 256>>>(qry, Q);
    k_filter<<<fblocks + 64, 256>>>(src, dst, ew, Ws, Wn, E, fblocks);
    k_fused <<<(Q + QT - 1) / QT, 256, RM_SMEM>>>(emb, bs, bn, Wr, br, qry,
                                                  (float*)d_out, Q);
}